// round 4
// baseline (speedup 1.0000x reference)
#include <cuda_runtime.h>
#include <cstdint>

#define T_STEPS 256
#define BATCH   8
#define NPROBES 4

typedef unsigned long long ull;

// ---------- f32x2 packed helpers (sm_103a) ----------
__device__ __forceinline__ ull pack2(float lo, float hi) {
    ull r; asm("mov.b64 %0, {%1, %2};" : "=l"(r) : "f"(lo), "f"(hi)); return r;
}
__device__ __forceinline__ void unpack2(ull a, float& lo, float& hi) {
    asm("mov.b64 {%0, %1}, %2;" : "=f"(lo), "=f"(hi) : "l"(a));
}
__device__ __forceinline__ ull add2(ull a, ull b) {
    ull r; asm("add.rn.f32x2 %0, %1, %2;" : "=l"(r) : "l"(a), "l"(b)); return r;
}
__device__ __forceinline__ ull fma2(ull a, ull b, ull c) {
    ull r; asm("fma.rn.f32x2 %0, %1, %2, %3;" : "=l"(r) : "l"(a), "l"(b), "l"(c)); return r;
}

// zero-initialized at module load; the last CTA of every launch resets them
// back to zero after reading, so every graph replay starts from zeros.
__device__ float    g_psum[NPROBES] = {0.f, 0.f, 0.f, 0.f};
__device__ unsigned g_ticket        = 0u;

// dynamic smem layout (bytes):
//   [0, 65536)        kk2  : ull[128][64]   (generic path only)
//   [65536, 98304)    halo : ull[2][32][64] boundary rows, double-buffered
//   [98304, 99328)    xsh  : float[256]
#define SMEM_BYTES 99328

// ---------------- time loop, templated on uniform-c fast path ----------------
template <bool UNI>
__device__ __forceinline__ void sim_loop(
    ull* __restrict__ halo, const float* __restrict__ xsh,
    const ull* __restrict__ kk2, ull Kc,
    ull (&y1lo)[8], ull (&y1hi)[8], ull (&y2lo)[8], ull (&y2hi)[8],
    int w, int l, int r0, bool src_owner,
    bool pown, const int (&pidx)[NPROBES], float (&pacc)[NPROBES],
    ull NEG4, ull CY2P, ull TWO2P)
{
    int cur = 0;
    for (int t = 0; t < T_STEPS; t++) {
        ull up_lo = 0, up_hi = 0, dn_lo = 0, dn_hi = 0;
        if (w > 0) {
            ulonglong2 h = *reinterpret_cast<const ulonglong2*>(
                &halo[cur * 2048 + (2 * (w - 1) + 1) * 64 + 2 * l]);
            up_lo = h.x; up_hi = h.y;
        }
        if (w < 15) {
            ulonglong2 h = *reinterpret_cast<const ulonglong2*>(
                &halo[cur * 2048 + (2 * (w + 1) + 0) * 64 + 2 * l]);
            dn_lo = h.x; dn_hi = h.y;
        }
        const float xt  = src_owner ? xsh[t] : 0.0f;
        const ull   xt2 = pack2(xt, 0.0f);

        ull above_lo = up_lo, above_hi = up_hi;
#pragma unroll
        for (int j = 0; j < 8; j++) {
            const ull v_lo = y1lo[j], v_hi = y1hi[j];
            ull below_lo = dn_lo, below_hi = dn_hi;
            if (j < 7) { below_lo = y1lo[j + 1]; below_hi = y1hi[j + 1]; }

            float vx, vy, vz, vw;
            unpack2(v_lo, vx, vy);
            unpack2(v_hi, vz, vw);

            float lf = __shfl_up_sync(0xffffffffu, vw, 1);
            float rt = __shfl_down_sync(0xffffffffu, vx, 1);
            if (l == 0)  lf = 0.f;
            if (l == 31) rt = 0.f;

            const ull P1 = pack2(lf, vx);
            const ull P2 = pack2(vy, vz);
            const ull P3 = pack2(vw, rt);

            ull lap_lo = add2(add2(above_lo, below_lo), add2(P1, P2));
            lap_lo = fma2(NEG4, v_lo, lap_lo);
            ull lap_hi = add2(add2(above_hi, below_hi), add2(P2, P3));
            lap_hi = fma2(NEG4, v_hi, lap_hi);

            ull kx, ky;
            if (UNI) {
                kx = Kc; ky = Kc;
            } else {
                const ulonglong2 kkp = *reinterpret_cast<const ulonglong2*>(
                    &kk2[(r0 + j) * 64 + 2 * l]);
                kx = kkp.x; ky = kkp.y;
            }

            ull nv_lo = fma2(kx, lap_lo, fma2(CY2P, y2lo[j], TWO2P));
            ull nv_hi = fma2(ky, lap_hi, fma2(CY2P, y2hi[j], TWO2P));

            if (j == 0) nv_lo = add2(nv_lo, xt2);   // source injection

            y2lo[j] = v_lo;  y2hi[j] = v_hi;
            y1lo[j] = nv_lo; y1hi[j] = nv_hi;
            above_lo = v_lo; above_hi = v_hi;
        }

        if (pown) {
#pragma unroll
            for (int p = 0; p < NPROBES; p++) {
                if (pidx[p] >= 0) {
                    float a, bf, val = 0.f;
                    switch (pidx[p]) {
#define GC(J) \
                        case 4*(J)+0: unpack2(y1lo[J], a, bf); val = a;  break; \
                        case 4*(J)+1: unpack2(y1lo[J], a, bf); val = bf; break; \
                        case 4*(J)+2: unpack2(y1hi[J], a, bf); val = a;  break; \
                        case 4*(J)+3: unpack2(y1hi[J], a, bf); val = bf; break;
                        GC(0) GC(1) GC(2) GC(3) GC(4) GC(5) GC(6) GC(7)
#undef GC
                    }
                    pacc[p] += val * val;
                }
            }
        }

        {
            ulonglong2 top; top.x = y1lo[0]; top.y = y1hi[0];
            ulonglong2 bot; bot.x = y1lo[7]; bot.y = y1hi[7];
            *reinterpret_cast<ulonglong2*>(&halo[(cur ^ 1) * 2048 + (2 * w + 0) * 64 + 2 * l]) = top;
            *reinterpret_cast<ulonglong2*>(&halo[(cur ^ 1) * 2048 + (2 * w + 1) * 64 + 2 * l]) = bot;
        }
        __syncthreads();
        cur ^= 1;
    }
}

__global__ __launch_bounds__(512, 1)
void wave_fused_kernel(const float* __restrict__ x,
                       const float* __restrict__ c,
                       const int* __restrict__ probes_i32,
                       float* __restrict__ out)
{
    extern __shared__ char smem_raw[];
    ull*   kk2  = reinterpret_cast<ull*>(smem_raw);
    ull*   halo = reinterpret_cast<ull*>(smem_raw + 65536);
    float* xsh  = reinterpret_cast<float*>(smem_raw + 98304);

    const int b   = blockIdx.x;
    const int tid = threadIdx.x;
    const int w   = tid >> 5;
    const int l   = tid & 31;
    const int r0  = w << 3;
    const int c0  = l << 2;

    const float dtb   = 0.5f * 0.005f;
    const float cy2s  = -1.0f - dtb;                   // -1.0025
    const float denom = 4.0f + (0.5f * 0.005f) / 0.5f; // 4.005
    const float invd  = 1.0f / denom;

    const ull NEG4  = pack2(-4.0f, -4.0f);
    const ull CY2P  = pack2(cy2s * invd, cy2s * invd);
    const ull TWO2P = pack2(2.0f * invd, 2.0f * invd);

    for (int t = tid; t < T_STEPS; t += 512)
        xsh[t] = x[t * BATCH + b];
    for (int i = tid; i < 2 * 32 * 64; i += 512)
        halo[i] = 0ull;

    // load c, fill generic kk2, and check uniformity
    const float cref = c[0];
    bool all_eq = true;
    ull y1lo[8], y1hi[8], y2lo[8], y2hi[8];
#pragma unroll
    for (int j = 0; j < 8; j++) {
        float4 cv = *reinterpret_cast<const float4*>(&c[(r0 + j) * 128 + c0]);
        all_eq = all_eq && (cv.x == cref) && (cv.y == cref) &&
                           (cv.z == cref) && (cv.w == cref);
        kk2[(r0 + j) * 64 + 2 * l]     = pack2(0.25f * cv.x * cv.x * invd,
                                               0.25f * cv.y * cv.y * invd);
        kk2[(r0 + j) * 64 + 2 * l + 1] = pack2(0.25f * cv.z * cv.z * invd,
                                               0.25f * cv.w * cv.w * invd);
        y1lo[j] = 0ull; y1hi[j] = 0ull;
        y2lo[j] = 0ull; y2hi[j] = 0ull;
    }
    const float kc = 0.25f * cref * cref * invd;
    const ull   Kc = pack2(kc, kc);

    // probe decoding (runtime dtype detection: int32 vs int64)
    int pxv[NPROBES], pyv[NPROBES];
    {
        int odd_or = probes_i32[1] | probes_i32[3] | probes_i32[5] | probes_i32[7];
        if (odd_or == 0) {
#pragma unroll
            for (int p = 0; p < NPROBES; p++) {
                pxv[p] = probes_i32[4 * p];
                pyv[p] = probes_i32[4 * p + 2];
            }
        } else {
#pragma unroll
            for (int p = 0; p < NPROBES; p++) {
                pxv[p] = probes_i32[2 * p];
                pyv[p] = probes_i32[2 * p + 1];
            }
        }
    }

    float pacc[NPROBES];
    int   pidx[NPROBES];
    bool  pown = false;
#pragma unroll
    for (int p = 0; p < NPROBES; p++) {
        pacc[p] = 0.f;
        int px = pxv[p], py = pyv[p];
        bool mine = (px >= r0) && (px < r0 + 8) && (py >= c0) && (py < c0 + 4);
        pidx[p] = mine ? ((px - r0) * 4 + (py - c0)) : -1;
        pown = pown || mine;
    }

    const bool src_owner = (w == 8) && (l == 16);

    const int uni = __syncthreads_and(all_eq ? 1 : 0);  // also the init barrier

    if (uni)
        sim_loop<true >(halo, xsh, kk2, Kc, y1lo, y1hi, y2lo, y2hi,
                        w, l, r0, src_owner, pown, pidx, pacc, NEG4, CY2P, TWO2P);
    else
        sim_loop<false>(halo, xsh, kk2, Kc, y1lo, y1hi, y2lo, y2hi,
                        w, l, r0, src_owner, pown, pidx, pacc, NEG4, CY2P, TWO2P);

#pragma unroll
    for (int p = 0; p < NPROBES; p++)
        if (pidx[p] >= 0) atomicAdd(&g_psum[p], pacc[p]);

    // ---- fused finalization: last CTA to arrive reduces + resets ----
    __syncthreads();          // all this CTA's atomics are issued
    __threadfence();          // and visible at device scope
    if (tid == 0) {
        unsigned ticket = atomicAdd(&g_ticket, 1u);
        if (ticket == BATCH - 1) {
            float v[NPROBES];
            float s = 0.f;
#pragma unroll
            for (int p = 0; p < NPROBES; p++) {
                v[p] = atomicAdd(&g_psum[p], 0.0f);   // coherent read via L2
                s += v[p];
            }
#pragma unroll
            for (int p = 0; p < NPROBES; p++) {
                out[p] = v[p] / s;
                atomicExch(&g_psum[p], 0.0f);          // reset for next replay
            }
            atomicExch(&g_ticket, 0u);
        }
    }
}

extern "C" void kernel_launch(void* const* d_in, const int* in_sizes, int n_in,
                              void* d_out, int out_size)
{
    const float* x      = (const float*)d_in[0];   // (256, 8) f32
    const float* c      = (const float*)d_in[1];   // (128, 128) f32
    const int*   probes = (const int*)d_in[2];     // (4, 2) int32 (or int64) — detected in-kernel
    float*       out    = (float*)d_out;           // (4,) f32

    cudaFuncSetAttribute(wave_fused_kernel,
                         cudaFuncAttributeMaxDynamicSharedMemorySize, SMEM_BYTES);

    wave_fused_kernel<<<BATCH, 512, SMEM_BYTES>>>(x, c, probes, out);
}